// round 9
// baseline (speedup 1.0000x reference)
#include <cuda_runtime.h>
#include <cuda_bf16.h>
#include <cstdint>

#define NODE_DIM 256
#define HIDDEN   128
#define MAX_NODES 100000

// ---------------- device scratch ----------------
// PQ stored with PERMUTED hidden layout per half:
//   position p = c*32 + nt*2 + j   holds true col  n = nt*8 + 2c + j
// (c = lane&3 quad-col, nt = 0..15, j = 0..1). W2 is permuted to match.
__device__ float         g_PQ [(size_t)MAX_NODES * 256];
__device__ __nv_bfloat16 g_Bhi[256 * 256];                  // B[n][k] = W1ab[k][n]
__device__ __nv_bfloat16 g_Blo[256 * 256];

// ---------------- helpers ----------------
__device__ __forceinline__ uint32_t smem_u32(const void* p) {
    uint32_t a;
    asm("{ .reg .u64 t; cvta.to.shared.u64 t, %1; cvt.u32.u64 %0, t; }" : "=r"(a) : "l"(p));
    return a;
}
__device__ __forceinline__ void ldsm4(uint32_t* r, uint32_t addr) {
    asm volatile("ldmatrix.sync.aligned.m8n8.x4.shared.b16 {%0,%1,%2,%3}, [%4];"
        : "=r"(r[0]), "=r"(r[1]), "=r"(r[2]), "=r"(r[3]) : "r"(addr));
}
__device__ __forceinline__ void mma_bf16(float* d, const uint32_t* a, const uint32_t* b) {
    asm volatile("mma.sync.aligned.m16n8k16.row.col.f32.bf16.bf16.f32 "
        "{%0,%1,%2,%3}, {%4,%5,%6,%7}, {%8,%9}, {%0,%1,%2,%3};"
        : "+f"(d[0]), "+f"(d[1]), "+f"(d[2]), "+f"(d[3])
        : "r"(a[0]), "r"(a[1]), "r"(a[2]), "r"(a[3]), "r"(b[0]), "r"(b[1]));
}
#define SW128(o) ((o) ^ (((o) >> 3) & 0x70))

union BP4 { __nv_bfloat16 b[4]; uint2 u; };
__device__ __forceinline__ void split4(const float4& v, uint2& uh, uint2& ul) {
    float x[4] = {v.x, v.y, v.z, v.w};
    BP4 hi, lo;
    #pragma unroll
    for (int t = 0; t < 4; t++) {
        hi.b[t] = __float2bfloat16(x[t]);
        lo.b[t] = __float2bfloat16(x[t] - __bfloat162float(hi.b[t]));
    }
    uh = hi.u; ul = lo.u;
}

// ---------------------------------------------------------------------------
// conv_B: B[n][k] bf16 hi/lo.  n<128 -> W1[k][n]; n>=128 -> W1[256+k][n-128]
// ---------------------------------------------------------------------------
__global__ void conv_B_kernel(const float* __restrict__ W1) {
    int idx = blockIdx.x * blockDim.x + threadIdx.x;   // 0..65535
    int n = idx >> 8, k = idx & 255;
    float w = (n < HIDDEN) ? W1[(size_t)k * HIDDEN + n]
                           : W1[(size_t)(256 + k) * HIDDEN + (n - HIDDEN)];
    __nv_bfloat16 hi = __float2bfloat16(w);
    __nv_bfloat16 lo = __float2bfloat16(w - __bfloat162float(hi));
    g_Bhi[idx] = hi;
    g_Blo[idx] = lo;
}

// ---------------------------------------------------------------------------
// Phase 1: PQ = z @ [W1a|W1b], mma.sync bf16 3-term split, fused z convert.
// Single K-pass: 512 threads, 16 warps = 8 m-tiles x 2 N-halves.
// Epilogue writes PERMUTED layout; b1 folded into P half.
// ---------------------------------------------------------------------------
#define SA_HI 0
#define SA_LO 16384
#define SB_HI 32768
#define SB_LO 65536
#define GSMEM 98304

__global__ __launch_bounds__(512, 1) void gemm_tc_kernel(
    const float* __restrict__ z, const float* __restrict__ b1, int M)
{
    extern __shared__ char smem[];
    const uint32_t sb = smem_u32(smem);
    const int tid  = threadIdx.x;
    const int warp = tid >> 5;
    const int lane = tid & 31;
    const int half = warp >> 3;
    const int wm   = warp & 7;
    const int m0   = blockIdx.x * 128;

    const uint32_t a_row  = wm * 16 + ((lane >> 3) & 1) * 8 + (lane & 7);
    const uint32_t a_koff = (lane >> 4) * 16;
    const uint32_t b_rowi = ((lane >> 4) & 1) * 8 + (lane & 7);
    const uint32_t b_koff = ((lane >> 3) & 1) * 16;

    float acc[16][4];
    #pragma unroll
    for (int i = 0; i < 16; i++)
        #pragma unroll
        for (int j = 0; j < 4; j++) acc[i][j] = 0.f;

    #pragma unroll 1
    for (int ch = 0; ch < 4; ch++) {
        const int kc = ch * 64;
        __syncthreads();
        #pragma unroll
        for (int j = 0; j < 4; j++) {
            int id = j * 512 + tid;
            int r = id >> 4, c = id & 15;
            float4 v = make_float4(0.f, 0.f, 0.f, 0.f);
            if (m0 + r < M)
                v = *(const float4*)(z + (size_t)(m0 + r) * 256 + kc + c * 4);
            uint2 uh, ul;
            split4(v, uh, ul);
            uint32_t so = SW128((uint32_t)(r * 128 + c * 8));
            *(uint2*)(smem + SA_HI + so) = uh;
            *(uint2*)(smem + SA_LO + so) = ul;
        }
        #pragma unroll
        for (int j = 0; j < 4; j++) {
            int id = j * 512 + tid;
            int r = id >> 3, c = id & 7;
            size_t off = (size_t)r * 256 + kc + c * 8;
            uint4 vh = *(const uint4*)(g_Bhi + off);
            uint4 vl = *(const uint4*)(g_Blo + off);
            uint32_t so = SW128((uint32_t)(r * 128 + c * 16));
            *(uint4*)(smem + SB_HI + so) = vh;
            *(uint4*)(smem + SB_LO + so) = vl;
        }
        __syncthreads();

        #pragma unroll
        for (int kt = 0; kt < 4; kt++) {
            uint32_t ah[4], al[4];
            uint32_t aoff = SW128(a_row * 128 + kt * 32 + a_koff);
            ldsm4(ah, sb + SA_HI + aoff);
            ldsm4(al, sb + SA_LO + aoff);
            #pragma unroll
            for (int ntp = 0; ntp < 8; ntp++) {
                uint32_t boff = SW128((uint32_t)((half * 128 + ntp * 16 + b_rowi) * 128
                                                 + kt * 32 + b_koff));
                uint32_t bh[4], bl[4];
                ldsm4(bh, sb + SB_HI + boff);
                ldsm4(bl, sb + SB_LO + boff);
                mma_bf16(acc[2 * ntp],     ah, bh);
                mma_bf16(acc[2 * ntp],     ah, bl);
                mma_bf16(acc[2 * ntp],     al, bh);
                mma_bf16(acc[2 * ntp + 1], ah, bh + 2);
                mma_bf16(acc[2 * ntp + 1], ah, bl + 2);
                mma_bf16(acc[2 * ntp + 1], al, bh + 2);
            }
        }
    }

    // Epilogue: permuted write. true col (within half) = nt*8 + 2c + j,
    // stored at position p = c*32 + nt*2 + j.
    const int r0 = m0 + wm * 16 + (lane >> 2);
    const int c  = lane & 3;
    #pragma unroll
    for (int nt = 0; nt < 16; nt++) {
        int ntrue = nt * 8 + 2 * c;             // true col for b1
        float2 bb = make_float2(0.f, 0.f);
        if (half == 0) bb = __ldg((const float2*)(b1 + ntrue));
        int p0 = half * 128 + c * 32 + nt * 2;
        if (r0 < M)
            *(float2*)(g_PQ + (size_t)r0 * 256 + p0) =
                make_float2(acc[nt][0] + bb.x, acc[nt][1] + bb.y);
        if (r0 + 8 < M)
            *(float2*)(g_PQ + (size_t)(r0 + 8) * 256 + p0) =
                make_float2(acc[nt][2] + bb.x, acc[nt][3] + bb.y);
    }
}

// ---------------------------------------------------------------------------
// Phase 2: 128-edge tiles, ea@W1c on tensor cores, permuted-layout gathers:
// per edge-row each thread reads ONE contiguous 128B block of P and of Q
// (8 LDG.128 each, all hitting the same L1 line).
// ---------------------------------------------------------------------------
#define TE 128

__global__ __launch_bounds__(256, 2) void edge_kernel(
    const int* __restrict__ eli, const float* __restrict__ ea,
    const float* __restrict__ W1, const float* __restrict__ W2,
    const float* __restrict__ b2, float* __restrict__ out, int E)
{
    __shared__ __align__(16) __nv_bfloat16 sAh[128 * 40];
    __shared__ __align__(16) __nv_bfloat16 sAl[128 * 40];
    __shared__ __align__(16) __nv_bfloat16 sWh[128 * 40];
    __shared__ __align__(16) __nv_bfloat16 sWl[128 * 40];
    __shared__ float sW2[128];     // permuted
    __shared__ int   sS[TE];
    __shared__ int   sD[TE];

    const int tid  = threadIdx.x;
    const int warp = tid >> 5;
    const int lane = tid & 31;

    #pragma unroll
    for (int j = 0; j < 16; j++) {
        int id = j * 256 + tid;            // 0..4095
        int k = id >> 7, n = id & 127;
        float w = W1[(size_t)(512 + k) * HIDDEN + n];
        __nv_bfloat16 hi = __float2bfloat16(w);
        sWh[n * 40 + k] = hi;
        sWl[n * 40 + k] = __float2bfloat16(w - __bfloat162float(hi));
    }
    if (tid < 128) {
        // position p -> true col: c = p>>5, nt = (p&31)>>1, j = p&1
        int c = tid >> 5, rem = tid & 31;
        sW2[tid] = W2[(rem >> 1) * 8 + 2 * c + (rem & 1)];
    }
    const float b2v = b2[0];
    __syncthreads();

    const int cq = lane & 3;
    float4 w2r[8];
    #pragma unroll
    for (int f = 0; f < 8; f++)
        w2r[f] = *(const float4*)(&sW2[cq * 32 + 4 * f]);

    const uint32_t sbAh = smem_u32(sAh), sbAl = smem_u32(sAl);
    const uint32_t sbWh = smem_u32(sWh), sbWl = smem_u32(sWl);

    const uint32_t a_row  = warp * 16 + ((lane >> 3) & 1) * 8 + (lane & 7);
    const uint32_t a_koff = (lane >> 4) * 16;
    const uint32_t b_rowi = ((lane >> 4) & 1) * 8 + (lane & 7);
    const uint32_t b_koff = ((lane >> 3) & 1) * 16;

    const int ntiles = (E + TE - 1) / TE;

    for (int tile = blockIdx.x; tile < ntiles; tile += gridDim.x) {
        const int e0 = tile * TE;
        __syncthreads();

        if (tid < TE) {
            int e = e0 + tid;
            sS[tid] = (e < E) ? eli[e] : 0;
        } else {
            int e = e0 + (tid - TE);
            sD[tid - TE] = (e < E) ? eli[(size_t)E + e] : 0;
        }

        #pragma unroll
        for (int j = 0; j < 4; j++) {
            int id = j * 256 + tid;
            int e = id >> 3, c4 = id & 7;
            float4 v = make_float4(0.f, 0.f, 0.f, 0.f);
            if (e0 + e < E)
                v = *(const float4*)(ea + (size_t)(e0 + e) * 32 + c4 * 4);
            uint2 uh, ul;
            split4(v, uh, ul);
            *(uint2*)(sAh + e * 40 + c4 * 4) = uh;
            *(uint2*)(sAl + e * 40 + c4 * 4) = ul;
        }
        __syncthreads();

        float acc[16][4];
        #pragma unroll
        for (int i = 0; i < 16; i++)
            #pragma unroll
            for (int j = 0; j < 4; j++) acc[i][j] = 0.f;

        #pragma unroll
        for (int kt = 0; kt < 2; kt++) {
            uint32_t ah[4], al[4];
            uint32_t aoff = a_row * 80 + kt * 32 + a_koff;
            ldsm4(ah, sbAh + aoff);
            ldsm4(al, sbAl + aoff);
            #pragma unroll
            for (int ntp = 0; ntp < 8; ntp++) {
                uint32_t boff = (ntp * 16 + b_rowi) * 80 + kt * 32 + b_koff;
                uint32_t bh[4], bl[4];
                ldsm4(bh, sbWh + boff);
                ldsm4(bl, sbWl + boff);
                mma_bf16(acc[2 * ntp],     ah, bh);
                mma_bf16(acc[2 * ntp],     ah, bl);
                mma_bf16(acc[2 * ntp],     al, bh);
                mma_bf16(acc[2 * ntp + 1], ah, bh + 2);
                mma_bf16(acc[2 * ntp + 1], ah, bl + 2);
                mma_bf16(acc[2 * ntp + 1], al, bh + 2);
            }
        }

        // Epilogue: permuted gathers. Thread reads its contiguous 128B block.
        #pragma unroll
        for (int i = 0; i < 2; i++) {
            int eloc = warp * 16 + (lane >> 2) + 8 * i;
            int e    = e0 + eloc;
            int s    = sS[eloc];
            int d    = sD[eloc];
            const float* pb = g_PQ + (size_t)s * 256 + cq * 32;
            const float* qb = g_PQ + (size_t)d * 256 + 128 + cq * 32;
            float part = 0.f;
            #pragma unroll
            for (int f = 0; f < 8; f++) {
                float4 p4 = __ldg((const float4*)(pb + 4 * f));
                float4 q4 = __ldg((const float4*)(qb + 4 * f));
                // float4 element e -> acc[2f + (e>>1)][2i + (e&1)]
                float h0 = fmaxf(acc[2 * f][2 * i]         + p4.x + q4.x, 0.f);
                float h1 = fmaxf(acc[2 * f][2 * i + 1]     + p4.y + q4.y, 0.f);
                float h2 = fmaxf(acc[2 * f + 1][2 * i]     + p4.z + q4.z, 0.f);
                float h3 = fmaxf(acc[2 * f + 1][2 * i + 1] + p4.w + q4.w, 0.f);
                part = fmaf(h0, w2r[f].x, fmaf(h1, w2r[f].y,
                       fmaf(h2, w2r[f].z, fmaf(h3, w2r[f].w, part))));
            }
            part += __shfl_xor_sync(0xffffffffu, part, 1);
            part += __shfl_xor_sync(0xffffffffu, part, 2);
            if ((lane & 3) == 0 && e < E)
                out[e] = part + b2v;
        }
    }
}

// ---------------------------------------------------------------------------
extern "C" void kernel_launch(void* const* d_in, const int* in_sizes, int n_in,
                              void* d_out, int out_size) {
    const float* z   = (const float*)d_in[0];
    const int*   eli = (const int*)d_in[1];      // int32 (JAX canonicalized)
    const float* ea  = (const float*)d_in[2];
    const float* W1  = (const float*)d_in[3];
    const float* b1  = (const float*)d_in[4];
    const float* W2  = (const float*)d_in[5];
    const float* b2  = (const float*)d_in[6];
    float* out = (float*)d_out;

    int M = in_sizes[0] / NODE_DIM;   // 100000
    int E = out_size;                 // 1000000

    cudaFuncSetAttribute(gemm_tc_kernel,
                         cudaFuncAttributeMaxDynamicSharedMemorySize, GSMEM);

    conv_B_kernel<<<256, 256>>>(W1);

    int gblocks = (M + 127) / 128;
    gemm_tc_kernel<<<gblocks, 512, GSMEM>>>(z, b1, M);

    int ntiles = (E + TE - 1) / TE;
    int nblk = ntiles < 296 ? ntiles : 296;
    edge_kernel<<<nblk, 256>>>(eli, ea, W1, W2, b2, out, E);
}

// round 10
// speedup vs baseline: 1.5293x; 1.5293x over previous
#include <cuda_runtime.h>
#include <cuda_bf16.h>
#include <cstdint>

#define NODE_DIM 256
#define HIDDEN   128
#define MAX_NODES 100000

// ---------------- device scratch ----------------
__device__ float         g_PQ [(size_t)MAX_NODES * 256];   // P(+b1)|Q per node
__device__ __nv_bfloat16 g_Bhi[256 * 256];                  // B[n][k] = W1ab[k][n]
__device__ __nv_bfloat16 g_Blo[256 * 256];

// ---------------- helpers ----------------
__device__ __forceinline__ uint32_t smem_u32(const void* p) {
    uint32_t a;
    asm("{ .reg .u64 t; cvta.to.shared.u64 t, %1; cvt.u32.u64 %0, t; }" : "=r"(a) : "l"(p));
    return a;
}
__device__ __forceinline__ void ldsm4(uint32_t* r, uint32_t addr) {
    asm volatile("ldmatrix.sync.aligned.m8n8.x4.shared.b16 {%0,%1,%2,%3}, [%4];"
        : "=r"(r[0]), "=r"(r[1]), "=r"(r[2]), "=r"(r[3]) : "r"(addr));
}
__device__ __forceinline__ void mma_bf16(float* d, const uint32_t* a, const uint32_t* b) {
    asm volatile("mma.sync.aligned.m16n8k16.row.col.f32.bf16.bf16.f32 "
        "{%0,%1,%2,%3}, {%4,%5,%6,%7}, {%8,%9}, {%0,%1,%2,%3};"
        : "+f"(d[0]), "+f"(d[1]), "+f"(d[2]), "+f"(d[3])
        : "r"(a[0]), "r"(a[1]), "r"(a[2]), "r"(a[3]), "r"(b[0]), "r"(b[1]));
}
#define SW128(o) ((o) ^ (((o) >> 3) & 0x70))

union BP4 { __nv_bfloat16 b[4]; uint2 u; };
__device__ __forceinline__ void split4(const float4& v, uint2& uh, uint2& ul) {
    float x[4] = {v.x, v.y, v.z, v.w};
    BP4 hi, lo;
    #pragma unroll
    for (int t = 0; t < 4; t++) {
        hi.b[t] = __float2bfloat16(x[t]);
        lo.b[t] = __float2bfloat16(x[t] - __bfloat162float(hi.b[t]));
    }
    uh = hi.u; ul = lo.u;
}

// ---------------------------------------------------------------------------
// conv_B: B[n][k] bf16 hi/lo.  n<128 -> W1[k][n]; n>=128 -> W1[256+k][n-128]
// ---------------------------------------------------------------------------
__global__ void conv_B_kernel(const float* __restrict__ W1) {
    int idx = blockIdx.x * blockDim.x + threadIdx.x;   // 0..65535
    int n = idx >> 8, k = idx & 255;
    float w = (n < HIDDEN) ? W1[(size_t)k * HIDDEN + n]
                           : W1[(size_t)(256 + k) * HIDDEN + (n - HIDDEN)];
    __nv_bfloat16 hi = __float2bfloat16(w);
    __nv_bfloat16 lo = __float2bfloat16(w - __bfloat162float(hi));
    g_Bhi[idx] = hi;
    g_Blo[idx] = lo;
}

// ---------------------------------------------------------------------------
// Phase 1 (unchanged from R8): PQ = z @ [W1a|W1b], mma.sync bf16 3-term split,
// fused z convert. Single K-pass, 512 threads. b1 folded into P half.
// ---------------------------------------------------------------------------
#define SA_HI 0
#define SA_LO 16384
#define SB_HI 32768
#define SB_LO 65536
#define GSMEM 98304

__global__ __launch_bounds__(512, 1) void gemm_tc_kernel(
    const float* __restrict__ z, const float* __restrict__ b1, int M)
{
    extern __shared__ char smem[];
    const uint32_t sb = smem_u32(smem);
    const int tid  = threadIdx.x;
    const int warp = tid >> 5;
    const int lane = tid & 31;
    const int half = warp >> 3;
    const int wm   = warp & 7;
    const int m0   = blockIdx.x * 128;

    const uint32_t a_row  = wm * 16 + ((lane >> 3) & 1) * 8 + (lane & 7);
    const uint32_t a_koff = (lane >> 4) * 16;
    const uint32_t b_rowi = ((lane >> 4) & 1) * 8 + (lane & 7);
    const uint32_t b_koff = ((lane >> 3) & 1) * 16;

    float acc[16][4];
    #pragma unroll
    for (int i = 0; i < 16; i++)
        #pragma unroll
        for (int j = 0; j < 4; j++) acc[i][j] = 0.f;

    #pragma unroll 1
    for (int ch = 0; ch < 4; ch++) {
        const int kc = ch * 64;
        __syncthreads();
        #pragma unroll
        for (int j = 0; j < 4; j++) {
            int id = j * 512 + tid;
            int r = id >> 4, c = id & 15;
            float4 v = make_float4(0.f, 0.f, 0.f, 0.f);
            if (m0 + r < M)
                v = *(const float4*)(z + (size_t)(m0 + r) * 256 + kc + c * 4);
            uint2 uh, ul;
            split4(v, uh, ul);
            uint32_t so = SW128((uint32_t)(r * 128 + c * 8));
            *(uint2*)(smem + SA_HI + so) = uh;
            *(uint2*)(smem + SA_LO + so) = ul;
        }
        #pragma unroll
        for (int j = 0; j < 4; j++) {
            int id = j * 512 + tid;
            int r = id >> 3, c = id & 7;
            size_t off = (size_t)r * 256 + kc + c * 8;
            uint4 vh = *(const uint4*)(g_Bhi + off);
            uint4 vl = *(const uint4*)(g_Blo + off);
            uint32_t so = SW128((uint32_t)(r * 128 + c * 16));
            *(uint4*)(smem + SB_HI + so) = vh;
            *(uint4*)(smem + SB_LO + so) = vl;
        }
        __syncthreads();

        #pragma unroll
        for (int kt = 0; kt < 4; kt++) {
            uint32_t ah[4], al[4];
            uint32_t aoff = SW128(a_row * 128 + kt * 32 + a_koff);
            ldsm4(ah, sb + SA_HI + aoff);
            ldsm4(al, sb + SA_LO + aoff);
            #pragma unroll
            for (int ntp = 0; ntp < 8; ntp++) {
                uint32_t boff = SW128((uint32_t)((half * 128 + ntp * 16 + b_rowi) * 128
                                                 + kt * 32 + b_koff));
                uint32_t bh[4], bl[4];
                ldsm4(bh, sb + SB_HI + boff);
                ldsm4(bl, sb + SB_LO + boff);
                mma_bf16(acc[2 * ntp],     ah, bh);
                mma_bf16(acc[2 * ntp],     ah, bl);
                mma_bf16(acc[2 * ntp],     al, bh);
                mma_bf16(acc[2 * ntp + 1], ah, bh + 2);
                mma_bf16(acc[2 * ntp + 1], ah, bl + 2);
                mma_bf16(acc[2 * ntp + 1], al, bh + 2);
            }
        }
    }

    const int r0 = m0 + wm * 16 + (lane >> 2);
    const int cb = 2 * (lane & 3);
    #pragma unroll
    for (int nt = 0; nt < 16; nt++) {
        int ncol = cb + nt * 8;
        float2 bb = make_float2(0.f, 0.f);
        if (half == 0) bb = __ldg((const float2*)(b1 + ncol));
        int n0 = half * 128 + ncol;
        if (r0 < M)
            *(float2*)(g_PQ + (size_t)r0 * 256 + n0) =
                make_float2(acc[nt][0] + bb.x, acc[nt][1] + bb.y);
        if (r0 + 8 < M)
            *(float2*)(g_PQ + (size_t)(r0 + 8) * 256 + n0) =
                make_float2(acc[nt][2] + bb.x, acc[nt][3] + bb.y);
    }
}

// ---------------------------------------------------------------------------
// Phase 2: BARRIER-FREE warp-independent pipeline. Each warp streams its own
// 16-edge tiles: indices in registers (shfl broadcast), warp-private EA smem,
// same MMA + R8 per-quad gather epilogue. No __syncthreads in the loop.
// ---------------------------------------------------------------------------
__global__ __launch_bounds__(256, 2) void edge_kernel(
    const int* __restrict__ eli, const float* __restrict__ ea,
    const float* __restrict__ W1, const float* __restrict__ W2,
    const float* __restrict__ b2, float* __restrict__ out, int E)
{
    __shared__ __align__(16) __nv_bfloat16 sAh[8 * 16 * 40];  // per-warp 16x40
    __shared__ __align__(16) __nv_bfloat16 sAl[8 * 16 * 40];
    __shared__ __align__(16) __nv_bfloat16 sWh[128 * 40];
    __shared__ __align__(16) __nv_bfloat16 sWl[128 * 40];
    __shared__ float sW2[128];

    const int tid  = threadIdx.x;
    const int warp = tid >> 5;
    const int lane = tid & 31;

    // One-time: W1c -> sW[n][k] hi/lo (rows of 40 bf16), W2
    #pragma unroll
    for (int j = 0; j < 16; j++) {
        int id = j * 256 + tid;            // 0..4095
        int k = id >> 7, n = id & 127;
        float w = W1[(size_t)(512 + k) * HIDDEN + n];
        __nv_bfloat16 hi = __float2bfloat16(w);
        sWh[n * 40 + k] = hi;
        sWl[n * 40 + k] = __float2bfloat16(w - __bfloat162float(hi));
    }
    if (tid < 128) sW2[tid] = W2[tid];
    const float b2v = b2[0];
    __syncthreads();            // only barrier: sW/sW2 ready

    __nv_bfloat16* wAh = sAh + warp * 640;
    __nv_bfloat16* wAl = sAl + warp * 640;
    const uint32_t sbAh = smem_u32(wAh), sbAl = smem_u32(wAl);
    const uint32_t sbWh = smem_u32(sWh), sbWl = smem_u32(sWl);

    const uint32_t a_row  = ((lane >> 3) & 1) * 8 + (lane & 7);   // 0..15 local
    const uint32_t a_koff = (lane >> 4) * 16;
    const uint32_t b_rowi = ((lane >> 4) & 1) * 8 + (lane & 7);
    const uint32_t b_koff = ((lane >> 3) & 1) * 16;
    const int cb = 2 * (lane & 3);

    const int ntiles = (E + 15) / 16;                 // 16-edge tiles
    const int gw     = blockIdx.x * 8 + warp;         // global warp id
    const int nwarps = gridDim.x * 8;

    for (int t = gw; t < ntiles; t += nwarps) {
        const int e0 = t * 16;

        // indices -> registers (lane l<16: src of edge l; l>=16: dst of edge l-16)
        int e_ld = e0 + (lane & 15);
        int idxv = 0;
        if (e_ld < E) idxv = (lane < 16) ? eli[e_ld] : eli[(size_t)E + e_ld];

        // EA: 16 rows x 32 floats (contiguous 2KB) -> bf16 hi/lo, rows of 40
        #pragma unroll
        for (int jj = 0; jj < 4; jj++) {
            int id = jj * 32 + lane;        // 0..127 float4 slots
            int r = id >> 3, c4 = id & 7;
            float4 v = make_float4(0.f, 0.f, 0.f, 0.f);
            if (e0 + r < E)
                v = *(const float4*)(ea + (size_t)e0 * 32 + id * 4);
            uint2 uh, ul;
            split4(v, uh, ul);
            *(uint2*)(wAh + r * 40 + c4 * 4) = uh;
            *(uint2*)(wAl + r * 40 + c4 * 4) = ul;
        }
        __syncwarp();

        // MMA: D[16e x 128n] = EA @ W1c, 3-term split
        float acc[16][4];
        #pragma unroll
        for (int i = 0; i < 16; i++)
            #pragma unroll
            for (int j = 0; j < 4; j++) acc[i][j] = 0.f;

        #pragma unroll
        for (int kt = 0; kt < 2; kt++) {
            uint32_t ah[4], al[4];
            uint32_t aoff = a_row * 80 + kt * 32 + a_koff;
            ldsm4(ah, sbAh + aoff);
            ldsm4(al, sbAl + aoff);
            #pragma unroll
            for (int ntp = 0; ntp < 8; ntp++) {
                uint32_t boff = (ntp * 16 + b_rowi) * 80 + kt * 32 + b_koff;
                uint32_t bh[4], bl[4];
                ldsm4(bh, sbWh + boff);
                ldsm4(bl, sbWl + boff);
                mma_bf16(acc[2 * ntp],     ah, bh);
                mma_bf16(acc[2 * ntp],     ah, bl);
                mma_bf16(acc[2 * ntp],     al, bh);
                mma_bf16(acc[2 * ntp + 1], ah, bh + 2);
                mma_bf16(acc[2 * ntp + 1], ah, bl + 2);
                mma_bf16(acc[2 * ntp + 1], al, bh + 2);
            }
        }
        __syncwarp();   // wAh/wAl consumed; safe to overwrite next iter

        // Epilogue (R8 structure): per-quad gathers, relu, dot W2, quad reduce
        #pragma unroll
        for (int i = 0; i < 2; i++) {
            int j    = (lane >> 2) + 8 * i;           // local edge 0..15
            int e    = e0 + j;
            int s    = __shfl_sync(0xffffffffu, idxv, j);
            int d    = __shfl_sync(0xffffffffu, idxv, j + 16);
            const float* pb = g_PQ + (size_t)s * 256;
            const float* qb = g_PQ + (size_t)d * 256 + 128;
            float part = 0.f;
            #pragma unroll
            for (int nt = 0; nt < 16; nt++) {
                int col = nt * 8 + cb;
                float2 p  = __ldg((const float2*)(pb + col));
                float2 q  = __ldg((const float2*)(qb + col));
                float2 w2 = *(const float2*)(&sW2[col]);
                float h0 = fmaxf(acc[nt][2 * i]     + p.x + q.x, 0.f);
                float h1 = fmaxf(acc[nt][2 * i + 1] + p.y + q.y, 0.f);
                part = fmaf(h0, w2.x, fmaf(h1, w2.y, part));
            }
            part += __shfl_xor_sync(0xffffffffu, part, 1);
            part += __shfl_xor_sync(0xffffffffu, part, 2);
            if ((lane & 3) == 0 && e < E)
                out[e] = part + b2v;
        }
    }
}

// ---------------------------------------------------------------------------
extern "C" void kernel_launch(void* const* d_in, const int* in_sizes, int n_in,
                              void* d_out, int out_size) {
    const float* z   = (const float*)d_in[0];
    const int*   eli = (const int*)d_in[1];      // int32 (JAX canonicalized)
    const float* ea  = (const float*)d_in[2];
    const float* W1  = (const float*)d_in[3];
    const float* b1  = (const float*)d_in[4];
    const float* W2  = (const float*)d_in[5];
    const float* b2  = (const float*)d_in[6];
    float* out = (float*)d_out;

    int M = in_sizes[0] / NODE_DIM;   // 100000
    int E = out_size;                 // 1000000

    cudaFuncSetAttribute(gemm_tc_kernel,
                         cudaFuncAttributeMaxDynamicSharedMemorySize, GSMEM);

    conv_B_kernel<<<256, 256>>>(W1);

    int gblocks = (M + 127) / 128;
    gemm_tc_kernel<<<gblocks, 512, GSMEM>>>(z, b1, M);

    edge_kernel<<<296, 256>>>(eli, ea, W1, W2, b2, out, E);
}

// round 11
// speedup vs baseline: 1.5810x; 1.0338x over previous
#include <cuda_runtime.h>
#include <cuda_bf16.h>
#include <cstdint>

#define NODE_DIM 256
#define HIDDEN   128
#define MAX_NODES 100000

// ---------------- device scratch ----------------
__device__ float         g_PQ [(size_t)MAX_NODES * 256];   // P(+b1)|Q per node
__device__ __nv_bfloat16 g_Bhi[256 * 256];                  // B[n][k] = W1ab[k][n]
__device__ __nv_bfloat16 g_Blo[256 * 256];

// ---------------- helpers ----------------
__device__ __forceinline__ uint32_t smem_u32(const void* p) {
    uint32_t a;
    asm("{ .reg .u64 t; cvta.to.shared.u64 t, %1; cvt.u32.u64 %0, t; }" : "=r"(a) : "l"(p));
    return a;
}
__device__ __forceinline__ void ldsm4(uint32_t* r, uint32_t addr) {
    asm volatile("ldmatrix.sync.aligned.m8n8.x4.shared.b16 {%0,%1,%2,%3}, [%4];"
        : "=r"(r[0]), "=r"(r[1]), "=r"(r[2]), "=r"(r[3]) : "r"(addr));
}
__device__ __forceinline__ void mma_bf16(float* d, const uint32_t* a, const uint32_t* b) {
    asm volatile("mma.sync.aligned.m16n8k16.row.col.f32.bf16.bf16.f32 "
        "{%0,%1,%2,%3}, {%4,%5,%6,%7}, {%8,%9}, {%0,%1,%2,%3};"
        : "+f"(d[0]), "+f"(d[1]), "+f"(d[2]), "+f"(d[3])
        : "r"(a[0]), "r"(a[1]), "r"(a[2]), "r"(a[3]), "r"(b[0]), "r"(b[1]));
}
#define SW128(o) ((o) ^ (((o) >> 3) & 0x70))

union BP4 { __nv_bfloat16 b[4]; uint2 u; };
__device__ __forceinline__ void split4(const float4& v, uint2& uh, uint2& ul) {
    float x[4] = {v.x, v.y, v.z, v.w};
    BP4 hi, lo;
    #pragma unroll
    for (int t = 0; t < 4; t++) {
        hi.b[t] = __float2bfloat16(x[t]);
        lo.b[t] = __float2bfloat16(x[t] - __bfloat162float(hi.b[t]));
    }
    uh = hi.u; ul = lo.u;
}

// ---------------------------------------------------------------------------
// conv_B: B[n][k] bf16 hi/lo.  n<128 -> W1[k][n]; n>=128 -> W1[256+k][n-128]
// ---------------------------------------------------------------------------
__global__ void conv_B_kernel(const float* __restrict__ W1) {
    int idx = blockIdx.x * blockDim.x + threadIdx.x;   // 0..65535
    int n = idx >> 8, k = idx & 255;
    float w = (n < HIDDEN) ? W1[(size_t)k * HIDDEN + n]
                           : W1[(size_t)(256 + k) * HIDDEN + (n - HIDDEN)];
    __nv_bfloat16 hi = __float2bfloat16(w);
    __nv_bfloat16 lo = __float2bfloat16(w - __bfloat162float(hi));
    g_Bhi[idx] = hi;
    g_Blo[idx] = lo;
}

// ---------------------------------------------------------------------------
// Phase 1: PQ = z @ [W1a|W1b], mma.sync bf16 3-term split, fused z convert.
// CTA = 128 rows x 256 cols, 512 threads. Warp tile = 32 rows x 64 cols
// (4x4 warp grid) -> B-ldsm per warp halved vs 16x128 tiling.
// b1 folded into P half.
// ---------------------------------------------------------------------------
#define SA_HI 0
#define SA_LO 16384
#define SB_HI 32768
#define SB_LO 65536
#define GSMEM 98304

__global__ __launch_bounds__(512, 1) void gemm_tc_kernel(
    const float* __restrict__ z, const float* __restrict__ b1, int M)
{
    extern __shared__ char smem[];
    const uint32_t sb = smem_u32(smem);
    const int tid  = threadIdx.x;
    const int warp = tid >> 5;
    const int lane = tid & 31;
    const int wr   = warp & 3;            // warp row group (32 rows)
    const int wc   = warp >> 2;           // warp col group (64 cols)
    const int m0   = blockIdx.x * 128;

    const uint32_t a_rbase = wr * 32 + ((lane >> 3) & 1) * 8 + (lane & 7);
    const uint32_t a_koff  = (lane >> 4) * 16;
    const uint32_t b_rowi  = ((lane >> 4) & 1) * 8 + (lane & 7);
    const uint32_t b_koff  = ((lane >> 3) & 1) * 16;

    float acc[2][8][4];
    #pragma unroll
    for (int mt = 0; mt < 2; mt++)
        #pragma unroll
        for (int i = 0; i < 8; i++)
            #pragma unroll
            for (int j = 0; j < 4; j++) acc[mt][i][j] = 0.f;

    #pragma unroll 1
    for (int ch = 0; ch < 4; ch++) {
        const int kc = ch * 64;
        __syncthreads();
        // A: z fp32 (128 x 64) -> bf16 hi/lo in-kernel, SW128 rows of 128B
        #pragma unroll
        for (int j = 0; j < 4; j++) {
            int id = j * 512 + tid;
            int r = id >> 4, c = id & 15;
            float4 v = make_float4(0.f, 0.f, 0.f, 0.f);
            if (m0 + r < M)
                v = *(const float4*)(z + (size_t)(m0 + r) * 256 + kc + c * 4);
            uint2 uh, ul;
            split4(v, uh, ul);
            uint32_t so = SW128((uint32_t)(r * 128 + c * 8));
            *(uint2*)(smem + SA_HI + so) = uh;
            *(uint2*)(smem + SA_LO + so) = ul;
        }
        // B: 256 n-rows x 64 k bf16 hi/lo
        #pragma unroll
        for (int j = 0; j < 4; j++) {
            int id = j * 512 + tid;
            int r = id >> 3, c = id & 7;
            size_t off = (size_t)r * 256 + kc + c * 8;
            uint4 vh = *(const uint4*)(g_Bhi + off);
            uint4 vl = *(const uint4*)(g_Blo + off);
            uint32_t so = SW128((uint32_t)(r * 128 + c * 16));
            *(uint4*)(smem + SB_HI + so) = vh;
            *(uint4*)(smem + SB_LO + so) = vl;
        }
        __syncthreads();

        #pragma unroll
        for (int kt = 0; kt < 4; kt++) {
            uint32_t ah[2][4], al[2][4];
            #pragma unroll
            for (int mt = 0; mt < 2; mt++) {
                uint32_t aoff = SW128((a_rbase + mt * 16) * 128 + kt * 32 + a_koff);
                ldsm4(ah[mt], sb + SA_HI + aoff);
                ldsm4(al[mt], sb + SA_LO + aoff);
            }
            #pragma unroll
            for (int bg = 0; bg < 4; bg++) {
                uint32_t boff = SW128((uint32_t)((wc * 64 + bg * 16 + b_rowi) * 128
                                                 + kt * 32 + b_koff));
                uint32_t bh[4], bl[4];
                ldsm4(bh, sb + SB_HI + boff);
                ldsm4(bl, sb + SB_LO + boff);
                #pragma unroll
                for (int mt = 0; mt < 2; mt++) {
                    mma_bf16(acc[mt][2 * bg],     ah[mt], bh);
                    mma_bf16(acc[mt][2 * bg],     ah[mt], bl);
                    mma_bf16(acc[mt][2 * bg],     al[mt], bh);
                    mma_bf16(acc[mt][2 * bg + 1], ah[mt], bh + 2);
                    mma_bf16(acc[mt][2 * bg + 1], ah[mt], bl + 2);
                    mma_bf16(acc[mt][2 * bg + 1], al[mt], bh + 2);
                }
            }
        }
    }

    // Epilogue: +b1 on P half (cols < 128), write g_PQ
    const int cbl = 2 * (lane & 3);
    #pragma unroll
    for (int mt = 0; mt < 2; mt++) {
        const int r0 = m0 + wr * 32 + mt * 16 + (lane >> 2);
        #pragma unroll
        for (int nn = 0; nn < 8; nn++) {
            int n0 = wc * 64 + nn * 8 + cbl;
            float2 bb = make_float2(0.f, 0.f);
            if (n0 < 128) bb = __ldg((const float2*)(b1 + n0));
            if (r0 < M)
                *(float2*)(g_PQ + (size_t)r0 * 256 + n0) =
                    make_float2(acc[mt][nn][0] + bb.x, acc[mt][nn][1] + bb.y);
            if (r0 + 8 < M)
                *(float2*)(g_PQ + (size_t)(r0 + 8) * 256 + n0) =
                    make_float2(acc[mt][nn][2] + bb.x, acc[mt][nn][3] + bb.y);
        }
    }
}

// ---------------------------------------------------------------------------
// Phase 2 (unchanged from R10): barrier-free warp-independent pipeline.
// ---------------------------------------------------------------------------
__global__ __launch_bounds__(256, 2) void edge_kernel(
    const int* __restrict__ eli, const float* __restrict__ ea,
    const float* __restrict__ W1, const float* __restrict__ W2,
    const float* __restrict__ b2, float* __restrict__ out, int E)
{
    __shared__ __align__(16) __nv_bfloat16 sAh[8 * 16 * 40];  // per-warp 16x40
    __shared__ __align__(16) __nv_bfloat16 sAl[8 * 16 * 40];
    __shared__ __align__(16) __nv_bfloat16 sWh[128 * 40];
    __shared__ __align__(16) __nv_bfloat16 sWl[128 * 40];
    __shared__ float sW2[128];

    const int tid  = threadIdx.x;
    const int warp = tid >> 5;
    const int lane = tid & 31;

    #pragma unroll
    for (int j = 0; j < 16; j++) {
        int id = j * 256 + tid;            // 0..4095
        int k = id >> 7, n = id & 127;
        float w = W1[(size_t)(512 + k) * HIDDEN + n];
        __nv_bfloat16 hi = __float2bfloat16(w);
        sWh[n * 40 + k] = hi;
        sWl[n * 40 + k] = __float2bfloat16(w - __bfloat162float(hi));
    }
    if (tid < 128) sW2[tid] = W2[tid];
    const float b2v = b2[0];
    __syncthreads();            // only barrier: sW/sW2 ready

    __nv_bfloat16* wAh = sAh + warp * 640;
    __nv_bfloat16* wAl = sAl + warp * 640;
    const uint32_t sbAh = smem_u32(wAh), sbAl = smem_u32(wAl);
    const uint32_t sbWh = smem_u32(sWh), sbWl = smem_u32(sWl);

    const uint32_t a_row  = ((lane >> 3) & 1) * 8 + (lane & 7);   // 0..15 local
    const uint32_t a_koff = (lane >> 4) * 16;
    const uint32_t b_rowi = ((lane >> 4) & 1) * 8 + (lane & 7);
    const uint32_t b_koff = ((lane >> 3) & 1) * 16;
    const int cb = 2 * (lane & 3);

    const int ntiles = (E + 15) / 16;                 // 16-edge tiles
    const int gw     = blockIdx.x * 8 + warp;         // global warp id
    const int nwarps = gridDim.x * 8;

    for (int t = gw; t < ntiles; t += nwarps) {
        const int e0 = t * 16;

        int e_ld = e0 + (lane & 15);
        int idxv = 0;
        if (e_ld < E) idxv = (lane < 16) ? eli[e_ld] : eli[(size_t)E + e_ld];

        #pragma unroll
        for (int jj = 0; jj < 4; jj++) {
            int id = jj * 32 + lane;        // 0..127 float4 slots
            int r = id >> 3, c4 = id & 7;
            float4 v = make_float4(0.f, 0.f, 0.f, 0.f);
            if (e0 + r < E)
                v = *(const float4*)(ea + (size_t)e0 * 32 + id * 4);
            uint2 uh, ul;
            split4(v, uh, ul);
            *(uint2*)(wAh + r * 40 + c4 * 4) = uh;
            *(uint2*)(wAl + r * 40 + c4 * 4) = ul;
        }
        __syncwarp();

        float acc[16][4];
        #pragma unroll
        for (int i = 0; i < 16; i++)
            #pragma unroll
            for (int j = 0; j < 4; j++) acc[i][j] = 0.f;

        #pragma unroll
        for (int kt = 0; kt < 2; kt++) {
            uint32_t ah[4], al[4];
            uint32_t aoff = a_row * 80 + kt * 32 + a_koff;
            ldsm4(ah, sbAh + aoff);
            ldsm4(al, sbAl + aoff);
            #pragma unroll
            for (int ntp = 0; ntp < 8; ntp++) {
                uint32_t boff = (ntp * 16 + b_rowi) * 80 + kt * 32 + b_koff;
                uint32_t bh[4], bl[4];
                ldsm4(bh, sbWh + boff);
                ldsm4(bl, sbWl + boff);
                mma_bf16(acc[2 * ntp],     ah, bh);
                mma_bf16(acc[2 * ntp],     ah, bl);
                mma_bf16(acc[2 * ntp],     al, bh);
                mma_bf16(acc[2 * ntp + 1], ah, bh + 2);
                mma_bf16(acc[2 * ntp + 1], ah, bl + 2);
                mma_bf16(acc[2 * ntp + 1], al, bh + 2);
            }
        }
        __syncwarp();

        #pragma unroll
        for (int i = 0; i < 2; i++) {
            int j    = (lane >> 2) + 8 * i;           // local edge 0..15
            int e    = e0 + j;
            int s    = __shfl_sync(0xffffffffu, idxv, j);
            int d    = __shfl_sync(0xffffffffu, idxv, j + 16);
            const float* pb = g_PQ + (size_t)s * 256;
            const float* qb = g_PQ + (size_t)d * 256 + 128;
            float part = 0.f;
            #pragma unroll
            for (int nt = 0; nt < 16; nt++) {
                int col = nt * 8 + cb;
                float2 p  = __ldg((const float2*)(pb + col));
                float2 q  = __ldg((const float2*)(qb + col));
                float2 w2 = *(const float2*)(&sW2[col]);
                float h0 = fmaxf(acc[nt][2 * i]     + p.x + q.x, 0.f);
                float h1 = fmaxf(acc[nt][2 * i + 1] + p.y + q.y, 0.f);
                part = fmaf(h0, w2.x, fmaf(h1, w2.y, part));
            }
            part += __shfl_xor_sync(0xffffffffu, part, 1);
            part += __shfl_xor_sync(0xffffffffu, part, 2);
            if ((lane & 3) == 0 && e < E)
                out[e] = part + b2v;
        }
    }
}

// ---------------------------------------------------------------------------
extern "C" void kernel_launch(void* const* d_in, const int* in_sizes, int n_in,
                              void* d_out, int out_size) {
    const float* z   = (const float*)d_in[0];
    const int*   eli = (const int*)d_in[1];      // int32 (JAX canonicalized)
    const float* ea  = (const float*)d_in[2];
    const float* W1  = (const float*)d_in[3];
    const float* b1  = (const float*)d_in[4];
    const float* W2  = (const float*)d_in[5];
    const float* b2  = (const float*)d_in[6];
    float* out = (float*)d_out;

    int M = in_sizes[0] / NODE_DIM;   // 100000
    int E = out_size;                 // 1000000

    cudaFuncSetAttribute(gemm_tc_kernel,
                         cudaFuncAttributeMaxDynamicSharedMemorySize, GSMEM);

    conv_B_kernel<<<256, 256>>>(W1);

    int gblocks = (M + 127) / 128;
    gemm_tc_kernel<<<gblocks, 512, GSMEM>>>(z, b1, M);

    edge_kernel<<<296, 256>>>(eli, ea, W1, W2, b2, out, E);
}